// round 5
// baseline (speedup 1.0000x reference)
#include <cuda_runtime.h>
#include <cstdint>

#define T_STEPS 1024
#define BATCH   1024
#define INDIM   128
#define HID     16
#define NROWS   (T_STEPS * BATCH)

// Scratch: per-(t,b) input projections, 4 gates x 16 hidden = 64 floats per row.
// Layout: g_proj[row*64 + gate*16 + n], row = t*BATCH + b.
// Padded by one extra timestep so the recurrence prefetch never branches.
__device__ float g_proj[(size_t)(NROWS + BATCH) * 64];

// ---------------- packed f32x2 helpers (sm_103a FFMA2 path) ----------------
__device__ __forceinline__ unsigned long long pack2(float x, float y) {
    unsigned long long r;
    asm("mov.b64 %0, {%1, %2};" : "=l"(r) : "f"(x), "f"(y));
    return r;
}
__device__ __forceinline__ unsigned long long ffma2(unsigned long long a,
                                                    unsigned long long b,
                                                    unsigned long long c) {
    unsigned long long d;
    asm("fma.rn.f32x2 %0, %1, %2, %3;" : "=l"(d) : "l"(a), "l"(b), "l"(c));
    return d;
}
__device__ __forceinline__ float2 unpack2(unsigned long long v) {
    float2 f;
    asm("mov.b64 {%0, %1}, %2;" : "=f"(f.x), "=f"(f.y) : "l"(v));
    return f;
}

// ---------------- Kernel 1: input projection GEMM ----------------
// g_proj[row][g*16+n] = b_g[n] + sum_{k<128} x[row][k] * W_g[n][k]
// W_g is [16,144] row-major; first 128 columns multiply x.
__global__ void __launch_bounds__(256) proj_gemm(
    const float* __restrict__ x,
    const float* __restrict__ Wf, const float* __restrict__ bf,
    const float* __restrict__ Wi, const float* __restrict__ bi,
    const float* __restrict__ Wg, const float* __restrict__ bg,
    const float* __restrict__ Wo, const float* __restrict__ bo)
{
    __shared__ unsigned long long Wsh[128][32];  // [k][n_pair], n = gate*16+j
    __shared__ float bsh[64];

    int tid = threadIdx.x;
    {
        const float* Ws[4] = {Wf, Wi, Wg, Wo};
        float* Wflat = (float*)Wsh;  // Wflat[k*64 + n]
        for (int idx = tid; idx < 64 * 128; idx += 256) {
            int n = idx >> 7;       // 0..63
            int k = idx & 127;      // 0..127
            Wflat[k * 64 + n] = Ws[n >> 4][(n & 15) * 144 + k];
        }
        if (tid < 64) {
            const float* bp = (tid < 16) ? bf : (tid < 32) ? bi : (tid < 48) ? bg : bo;
            bsh[tid] = bp[tid & 15];
        }
    }
    __syncthreads();

    size_t row = (size_t)blockIdx.x * 256 + tid;
    const float4* xr = (const float4*)(x + row * (size_t)INDIM);

    unsigned long long acc[32];
#pragma unroll
    for (int p = 0; p < 32; p++) acc[p] = 0ull;

#pragma unroll 2
    for (int kq = 0; kq < 32; kq++) {
        float4 xv = xr[kq];
#pragma unroll
        for (int kk = 0; kk < 4; kk++) {
            float xs = (kk == 0) ? xv.x : (kk == 1) ? xv.y : (kk == 2) ? xv.z : xv.w;
            unsigned long long xx = pack2(xs, xs);
            const ulonglong2* wrow = (const ulonglong2*)Wsh[kq * 4 + kk];
#pragma unroll
            for (int q = 0; q < 16; q++) {
                ulonglong2 w = wrow[q];
                acc[2 * q]     = ffma2(xx, w.x, acc[2 * q]);
                acc[2 * q + 1] = ffma2(xx, w.y, acc[2 * q + 1]);
            }
        }
    }

    float* op = g_proj + row * 64;
#pragma unroll
    for (int q = 0; q < 16; q++) {
        float2 a  = unpack2(acc[2 * q]);
        float2 b2 = unpack2(acc[2 * q + 1]);
        float4 o4;
        o4.x = a.x  + bsh[4 * q + 0];
        o4.y = a.y  + bsh[4 * q + 1];
        o4.z = b2.x + bsh[4 * q + 2];
        o4.w = b2.y + bsh[4 * q + 3];
        ((float4*)op)[q] = o4;
    }
}

// ---------------- fast activations ----------------
__device__ __forceinline__ float fsigmoid(float x) {
    return __fdividef(1.f, 1.f + __expf(-x));
}
__device__ __forceinline__ float ftanh(float x) {
    float e = __expf(-2.f * x);
    return __fdividef(1.f - e, 1.f + e);
}

// ---------------- Kernel 2: the recurrence ----------------
// One full warp per batch element. Lane l: j = l&15 (hidden unit),
// half = l>>4. half==0 owns gates (f,i); half==1 owns gates (g,o).
// h and c are replicated across the two halves (both halves hold h_j, c_j
// for their j). Gate values are exchanged once per step via shfl_xor(16).
__global__ void __launch_bounds__(128) recur(
    const float* __restrict__ Wf, const float* __restrict__ Wi,
    const float* __restrict__ Wg, const float* __restrict__ Wo,
    const float* __restrict__ thf, const float* __restrict__ thi,
    const float* __restrict__ thg, const float* __restrict__ tho,
    float* __restrict__ out)
{
    int warp = threadIdx.x >> 5;
    int b = blockIdx.x * 4 + warp;   // batch element 0..1023
    int l = threadIdx.x & 31;
    int j = l & 15;                  // hidden unit
    int half = l >> 4;               // 0: (f,i)   1: (g,o)
    int seg = l & 16;                // 16-lane segment base
    const unsigned FULL = 0xffffffffu;

    // Per-half gate weights/thetas. A = f or g, B = i or o.
    const float* WA  = half ? Wg  : Wf;
    const float* WB  = half ? Wo  : Wi;
    float tA = (half ? thg : thf)[j];
    float tB = (half ? tho : thi)[j];

    float wrA[16], wrB[16];
#pragma unroll
    for (int k = 0; k < 16; k++) {
        wrA[k] = WA[j * 144 + 128 + k];
        wrB[k] = WB[j * 144 + 128 + k];
    }

    float h = 0.f, c = 0.f;

    // Projection pointers: gates (f,i) at offsets j, 16+j; (g,o) at 32+j, 48+j.
    const float* pp = g_proj + (size_t)b * 64 + half * 32 + j;
    float pA = pp[0], pB = pp[16];

    for (int t = 0; t < T_STEPS; t++) {
        // Prefetch next step's projections (h-independent; padded row at t=T)
        const float* pn = pp + BATCH * 64;
        float nA = pn[0], nB = pn[16];

        // Recurrent matvec: a += sum_k h[k] * Wr[j][k]
        float aA = pA, aB = pB;
#pragma unroll
        for (int k = 0; k < 16; k++) {
            float hk = __shfl_sync(FULL, h, seg + k);
            aA = fmaf(hk, wrA[k], aA);
            aB = fmaf(hk, wrB[k], aB);
        }

        // qgate: sin, then inclusive prefix-sum over the 16-lane segment
        float sA = __sinf(aA + tA), sB = __sinf(aB + tB);
        float cA = sA, cB = sB;
#pragma unroll
        for (int off = 1; off < 16; off <<= 1) {
            float uA = __shfl_up_sync(FULL, cA, off, 16);
            float uB = __shfl_up_sync(FULL, cB, off, 16);
            if (j >= off) { cA += uA; cB += uB; }
        }
        float ttA = __shfl_sync(FULL, cA, seg + 15);
        float ttB = __shfl_sync(FULL, cB, seg + 15);
        float qA = (j == 0) ? (sA + ttA) : cA;
        float qB = (j == 0) ? (sB + ttB) : cB;

        // Activations: half0 -> sigmoid(qA)=f ; half1 -> tanh(qA)=g.
        // Shared exp: sigmoid uses exp(-x), tanh uses exp(-2x).
        float eA  = __expf(half ? (-2.f * qA) : (-qA));
        float vA  = __fdividef(half ? (1.f - eA) : 1.f, 1.f + eA);
        float vB  = fsigmoid(qB);    // i or o

        // Exchange gate values across halves
        float oA = __shfl_xor_sync(FULL, vA, 16);
        float oB = __shfl_xor_sync(FULL, vB, 16);
        float f_ = half ? oA : vA;
        float i_ = half ? oB : vB;
        float g_ = half ? vA : oA;
        float o_ = half ? vB : oB;

        c = f_ * c + i_ * g_;
        h = o_ * ftanh(c);

        if (half == 0)
            out[((size_t)t << 14) + (b << 4) + j] = h;

        pA = nA; pB = nB;
        pp = pn;
    }

    // Final hT, cT after outs[T,B,H]
    if (half == 0) {
        size_t base = (size_t)T_STEPS * BATCH * HID;
        out[base + (b << 4) + j] = h;
        out[base + BATCH * HID + (b << 4) + j] = c;
    }
}

// ---------------- launch ----------------
extern "C" void kernel_launch(void* const* d_in, const int* in_sizes, int n_in,
                              void* d_out, int out_size) {
    const float* x   = (const float*)d_in[0];
    const float* Wf  = (const float*)d_in[1];
    const float* bf  = (const float*)d_in[2];
    const float* thf = (const float*)d_in[3];
    const float* Wi  = (const float*)d_in[4];
    const float* bi  = (const float*)d_in[5];
    const float* thi = (const float*)d_in[6];
    const float* Wg  = (const float*)d_in[7];
    const float* bg  = (const float*)d_in[8];
    const float* thg = (const float*)d_in[9];
    const float* Wo  = (const float*)d_in[10];
    const float* bo  = (const float*)d_in[11];
    const float* tho = (const float*)d_in[12];
    float* out = (float*)d_out;

    proj_gemm<<<NROWS / 256, 256>>>(x, Wf, bf, Wi, bi, Wg, bg, Wo, bo);
    recur<<<BATCH / 4, 128>>>(Wf, Wi, Wg, Wo, thf, thi, thg, tho, out);
}